// round 14
// baseline (speedup 1.0000x reference)
#include <cuda_runtime.h>
#include <cuda_fp16.h>
#include <cstdint>
#include <cstddef>

// Problem constants
#define BBATCH 8
#define TT 1024
#define CC 1024
#define MM (BBATCH*TT)          // 8192 rows
#define C4 (4*CC)               // 4096
#define MEG (CC*CC)             // 1048576

// ---------------------------------------------------------------------------
// Scratch (static __device__ arrays; no allocation allowed)
// ---------------------------------------------------------------------------
__device__ __half g_rs [MM*CC];            // sigmoid(xn Wr^T); later ffn sigmoid gate
__device__ __half g_k  [MM*CC];
__device__ __half g_v  [MM*CC];
__device__ __half g_wf [MM*CC];
__device__ __half g_wb [MM*CC];
__device__ __half g_xnh[MM*CC];            // fp16 LN output (GEMM A)
__device__ __half g_rh [MM*CC];            // fp16 r*wkv (GEMM A)
__device__ __half g_kkh[(size_t)MM*C4];    // fp16 ffn hidden (GEMM A)
// packed fp16 weights (GEMM B, rows = output features, K contiguous)
__device__ __half g_wkv [(size_t)3*MEG];         // [Wr; Wk; Wv]
__device__ __half g_wo  [MEG];                   // Wo
__device__ __half g_wffn[(size_t)5*MEG];         // [Wfk; Wfr]
__device__ __half g_wfv [(size_t)4*MEG];         // Wfv

// ---------------------------------------------------------------------------
// PTX helpers
// ---------------------------------------------------------------------------
__device__ __forceinline__ void cp_async16(uint32_t sa, const void* gm) {
    asm volatile("cp.async.cg.shared.global [%0], [%1], 16;" :: "r"(sa), "l"(gm));
}
__device__ __forceinline__ void ldsm_x4(uint32_t* r, uint32_t addr) {
    asm volatile("ldmatrix.sync.aligned.m8n8.x4.shared.b16 {%0,%1,%2,%3}, [%4];"
                 : "=r"(r[0]), "=r"(r[1]), "=r"(r[2]), "=r"(r[3]) : "r"(addr));
}
__device__ __forceinline__ void mma_f16(float* c, const uint32_t* a, const uint32_t* b) {
    asm volatile(
        "mma.sync.aligned.m16n8k16.row.col.f32.f16.f16.f32 "
        "{%0,%1,%2,%3}, {%4,%5,%6,%7}, {%8,%9}, {%0,%1,%2,%3};"
        : "+f"(c[0]), "+f"(c[1]), "+f"(c[2]), "+f"(c[3])
        : "r"(a[0]), "r"(a[1]), "r"(a[2]), "r"(a[3]), "r"(b[0]), "r"(b[1]));
}
__device__ __forceinline__ uint32_t sw128(uint32_t off) {
    return off ^ ((off >> 3) & 0x70);
}
__device__ __forceinline__ float sigm(float x) { return 1.f / (1.f + __expf(-x)); }

// ---------------------------------------------------------------------------
// Persistent fp16 GEMM: out = epilogue( A[M,K] * B[N,K]^T ), accum f32
// CTA tile 128x128, BK=64 halves, 2-stage cp.async, 256 threads (8 warps),
// warp tile 64x32. Grid = min(tiles, 296) CTAs; each loops over tiles
// bn-major (consecutive CTAs share B tile in L2) — kills wave quantization.
// ---------------------------------------------------------------------------
#define EPI_ADD     0   // Cf = aux1 + acc                          (float out)
#define EPI_MADD    1   // Cf = aux1 + auxh * acc   (auxh fp16 gate, float out)
#define EPI_RKV     2   // region0: sigmoid->Ch ; region1: raw->h2 ; region2: raw->h3
#define EPI_FFN1    3   // col<4096: relu^2 -> Ch ; else: sigmoid -> h2

#define STG_BYTES 32768   // 16KB A (128x128B) + 16KB B
#define MTILES (MM/128)   // 64

template <int EPI>
__global__ __launch_bounds__(256, 2)
void gemm_h(const __half* __restrict__ A, const __half* __restrict__ Bw,
            float* __restrict__ Cf, __half* __restrict__ Ch,
            __half* __restrict__ h2, __half* __restrict__ h3,
            const float* __restrict__ aux1, const __half* __restrict__ auxh,
            int K, int totTiles)
{
    extern __shared__ char smem_raw[];
    const uint32_t sb = ((uint32_t)__cvta_generic_to_shared(smem_raw) + 127u) & ~127u;

    const int tid  = threadIdx.x;
    const int warp = tid >> 5;
    const int lane = tid & 31;
    const int wm   = (warp & 1) * 64;
    const int wn   = (warp >> 1) * 32;
    const int nK   = K >> 6;            // K tiles of 64 halves

    const int rowA = lane & 15;
    const int kA   = (lane >> 4) << 3;
    const int rowB = (lane & 7) + ((lane >> 4) << 3);
    const int kB   = ((lane >> 3) & 1) << 3;
    const int g    = lane >> 2, q = lane & 3;

    for (int tile = blockIdx.x; tile < totTiles; tile += gridDim.x) {
        const int bn = (tile / MTILES) * 128;    // bn-major ordering
        const int bm = (tile % MTILES) * 128;

        float acc[4][4][4];
        #pragma unroll
        for (int mt = 0; mt < 4; mt++)
            #pragma unroll
            for (int nt = 0; nt < 4; nt++)
                #pragma unroll
                for (int i = 0; i < 4; i++) acc[mt][nt][i] = 0.f;

        auto load_tile = [&](int kt, int s) {
            const __half* Ag = A  + (size_t)bm * K + kt * 64;
            const __half* Bg = Bw + (size_t)bn * K + kt * 64;
            uint32_t sA = sb + s * STG_BYTES;
            uint32_t sB = sA + 16384;
            #pragma unroll
            for (int i = 0; i < 4; i++) {
                int n = tid + i * 256;
                int row = n >> 3, c = n & 7;
                uint32_t sw = sw128((uint32_t)(row * 128 + c * 16));
                cp_async16(sA + sw, Ag + (size_t)row * K + c * 8);
                cp_async16(sB + sw, Bg + (size_t)row * K + c * 8);
            }
        };

        load_tile(0, 0);
        asm volatile("cp.async.commit_group;");

        for (int t = 0; t < nK; t++) {
            if (t + 1 < nK) {
                load_tile(t + 1, (t + 1) & 1);
                asm volatile("cp.async.commit_group;");
                asm volatile("cp.async.wait_group 1;");
            } else {
                asm volatile("cp.async.wait_group 0;");
            }
            __syncthreads();

            uint32_t sA = sb + (t & 1) * STG_BYTES;
            uint32_t sB = sA + 16384;

            #pragma unroll
            for (int ks = 0; ks < 4; ks++) {
                uint32_t a[4][4], b[4][2];
                #pragma unroll
                for (int mt = 0; mt < 4; mt++) {
                    int r = wm + mt * 16 + rowA;
                    uint32_t off = (uint32_t)(r * 128 + (ks * 16 + kA) * 2);
                    ldsm_x4(a[mt], sA + sw128(off));
                }
                #pragma unroll
                for (int nt2 = 0; nt2 < 2; nt2++) {
                    uint32_t rb[4];
                    int n = wn + nt2 * 16 + rowB;
                    uint32_t off = (uint32_t)(n * 128 + (ks * 16 + kB) * 2);
                    ldsm_x4(rb, sB + sw128(off));
                    b[nt2 * 2][0]     = rb[0]; b[nt2 * 2][1]     = rb[1];
                    b[nt2 * 2 + 1][0] = rb[2]; b[nt2 * 2 + 1][1] = rb[3];
                }
                #pragma unroll
                for (int mt = 0; mt < 4; mt++)
                    #pragma unroll
                    for (int nt = 0; nt < 4; nt++)
                        mma_f16(acc[mt][nt], a[mt], b[nt]);
            }
            __syncthreads();
        }

        // epilogue (register-only reads; smem free for next tile)
        #pragma unroll
        for (int mt = 0; mt < 4; mt++) {
            #pragma unroll
            for (int hv = 0; hv < 2; hv++) {
                int row = bm + wm + mt * 16 + g + hv * 8;
                #pragma unroll
                for (int nt = 0; nt < 4; nt++) {
                    int col = bn + wn + nt * 8 + q * 2;
                    float c0 = acc[mt][nt][hv * 2];
                    float c1 = acc[mt][nt][hv * 2 + 1];
                    if (EPI == EPI_ADD) {
                        size_t gi = (size_t)row * CC + col;
                        float2 a2 = *(const float2*)(aux1 + gi);
                        *(float2*)(Cf + gi) = make_float2(a2.x + c0, a2.y + c1);
                    } else if (EPI == EPI_MADD) {
                        size_t gi = (size_t)row * CC + col;
                        float2 a2 = *(const float2*)(aux1 + gi);
                        float2 s2 = __half22float2(*(const __half2*)(auxh + gi));
                        *(float2*)(Cf + gi) = make_float2(a2.x + s2.x * c0,
                                                          a2.y + s2.y * c1);
                    } else if (EPI == EPI_RKV) {
                        int region = col >> 10;            // uniform per CTA
                        int lc = col & (CC - 1);
                        size_t gi = (size_t)row * CC + lc;
                        if (region == 0)
                            *(__half2*)(Ch + gi) = __floats2half2_rn(sigm(c0), sigm(c1));
                        else if (region == 1)
                            *(__half2*)(h2 + gi) = __floats2half2_rn(c0, c1);
                        else
                            *(__half2*)(h3 + gi) = __floats2half2_rn(c0, c1);
                    } else { // EPI_FFN1
                        if (col < C4) {
                            float t0 = fmaxf(c0, 0.f), t1 = fmaxf(c1, 0.f);
                            *(__half2*)(Ch + (size_t)row * C4 + col) =
                                __floats2half2_rn(t0 * t0, t1 * t1);
                        } else {
                            size_t gi = (size_t)row * CC + (col - C4);
                            *(__half2*)(h2 + gi) = __floats2half2_rn(sigm(c0), sigm(c1));
                        }
                    }
                }
            }
        }
    }
}

// ---------------------------------------------------------------------------
// Single-launch weight conversion+packing — 16 elems/thread, 512 threads.
// ---------------------------------------------------------------------------
__global__ __launch_bounds__(512)
void cvt_all_kernel(const float* __restrict__ Wr,
                    const float* __restrict__ Wk,
                    const float* __restrict__ Wv,
                    const float* __restrict__ Wo,
                    const float* __restrict__ Wfk,
                    const float* __restrict__ Wfv,
                    const float* __restrict__ Wfr,
                    __half* __restrict__ wkv,
                    __half* __restrict__ wo,
                    __half* __restrict__ wffn,
                    __half* __restrict__ wfv) {
    const size_t i = ((size_t)blockIdx.x * 512 + threadIdx.x) * 16;
    const int region = blockIdx.x >> 7;           // 0..12, uniform per block
    const float* s; __half* d;
    if      (region < 1)  { s = Wr  + i;                     d = wkv  + i; }
    else if (region < 2)  { s = Wk  + (i - (size_t)MEG);     d = wkv  + i; }
    else if (region < 3)  { s = Wv  + (i - (size_t)2*MEG);   d = wkv  + i; }
    else if (region < 4)  { s = Wo  + (i - (size_t)3*MEG);   d = wo   + (i - (size_t)3*MEG); }
    else if (region < 8)  { s = Wfk + (i - (size_t)4*MEG);   d = wffn + (i - (size_t)4*MEG); }
    else if (region < 9)  { s = Wfr + (i - (size_t)8*MEG);   d = wffn + (i - (size_t)4*MEG); }
    else                  { s = Wfv + (i - (size_t)9*MEG);   d = wfv  + (i - (size_t)9*MEG); }
    #pragma unroll
    for (int h = 0; h < 2; h++) {
        float4 v0 = *(const float4*)(s + h * 8);
        float4 v1 = *(const float4*)(s + h * 8 + 4);
        __half2 h0 = __floats2half2_rn(v0.x, v0.y);
        __half2 h1 = __floats2half2_rn(v0.z, v0.w);
        __half2 h2 = __floats2half2_rn(v1.x, v1.y);
        __half2 h3 = __floats2half2_rn(v1.z, v1.w);
        uint4 pk;
        pk.x = *(uint32_t*)&h0; pk.y = *(uint32_t*)&h1;
        pk.z = *(uint32_t*)&h2; pk.w = *(uint32_t*)&h3;
        *(uint4*)(d + h * 8) = pk;
    }
}

// ---------------------------------------------------------------------------
// LayerNorm: one block per row (C=1024, 256 threads); fp16 output
// ---------------------------------------------------------------------------
__global__ void ln_kernel(const float* __restrict__ x,
                          const float* __restrict__ w,
                          const float* __restrict__ b,
                          __half* __restrict__ out) {
    int row = blockIdx.x;
    const float* xr = x + (size_t)row * CC;
    float s = 0.f, s2 = 0.f;
    float vals[4];
    #pragma unroll
    for (int i = 0; i < 4; i++) {
        float t = xr[threadIdx.x + i * 256];
        vals[i] = t;
        s += t; s2 += t * t;
    }
    #pragma unroll
    for (int o = 16; o; o >>= 1) {
        s  += __shfl_xor_sync(0xffffffffu, s,  o);
        s2 += __shfl_xor_sync(0xffffffffu, s2, o);
    }
    __shared__ float sh[34];
    int warp = threadIdx.x >> 5, lane = threadIdx.x & 31;
    if (lane == 0) { sh[warp] = s; sh[warp + 8] = s2; }
    __syncthreads();
    if (threadIdx.x < 32) {
        s  = (threadIdx.x < 8) ? sh[threadIdx.x]     : 0.f;
        s2 = (threadIdx.x < 8) ? sh[threadIdx.x + 8] : 0.f;
        #pragma unroll
        for (int o = 4; o; o >>= 1) {
            s  += __shfl_xor_sync(0xffffffffu, s,  o);
            s2 += __shfl_xor_sync(0xffffffffu, s2, o);
        }
        if (threadIdx.x == 0) {
            float mu  = s * (1.f / CC);
            float var = s2 * (1.f / CC) - mu * mu;
            sh[32] = mu;
            sh[33] = rsqrtf(var + 1e-5f);
        }
    }
    __syncthreads();
    float mu = sh[32], rs = sh[33];
    __half* orow = out + (size_t)row * CC;
    #pragma unroll
    for (int i = 0; i < 4; i++) {
        int col = threadIdx.x + i * 256;
        orow[col] = __float2half_rn((vals[i] - mu) * rs * w[col] + b[col]);
    }
}

// ---------------------------------------------------------------------------
// Chunked two-pass WKV scan — fp16 I/O, f32 math, single-exp steps
// (round-13 version; bit-exact vs two-exp form)
// ---------------------------------------------------------------------------
#define SCH 16
#define SLEN 64

__global__ __launch_bounds__(512)
void scan2_kernel(const float* __restrict__ decay,
                  const float* __restrict__ u,
                  const __half* __restrict__ k,
                  const __half* __restrict__ v,
                  __half* __restrict__ wf,
                  __half* __restrict__ wb) {
    __shared__ float sA[SCH][32], sB[SCH][32], sP[SCH][32];
    __shared__ float iA[SCH][32], iB[SCH][32], iP[SCH][32];

    const int chan  = threadIdx.x & 31;
    const int chunk = threadIdx.x >> 5;
    const int c     = blockIdx.x * 32 + chan;
    const int b     = blockIdx.y;
    const int dir   = blockIdx.z;

    const float w  = -__expf(decay[c]);
    const float uu = u[c];
    const size_t base = (size_t)b * TT * CC + c;
    const int s0 = chunk * SLEN;

    float aa = 0.f, bb = 0.f, pp = -1e38f;
    {
        int tm0 = dir ? (TT - 1 - s0) : s0;
        int dt  = dir ? -1 : 1;
        size_t off = base + (size_t)tm0 * CC;
        ptrdiff_t doff = (ptrdiff_t)dt * CC;
        #pragma unroll 4
        for (int t = 0; t < SLEN; ++t, off += doff) {
            float kk = __half2float(k[off]), vv = __half2float(v[off]);
            float pw = pp + w;
            float d  = pw - kk;
            bool  ge = (d >= 0.f);
            float e  = __expf(ge ? -d : d);        // exp(-|d|)
            float f1 = ge ? 1.f : e;
            float f2 = ge ? e   : 1.f;
            aa = f1 * aa + f2 * vv;
            bb = f1 * bb + f2;
            pp = ge ? pw : kk;
        }
    }
    sA[chunk][chan] = aa; sB[chunk][chan] = bb; sP[chunk][chan] = pp;
    __syncthreads();

    if (threadIdx.x < 32) {
        const int ch = threadIdx.x;
        float pa = 0.f, pb = 0.f, ppf = -1e38f;
        const float Lw = SLEN * w;
        #pragma unroll
        for (int j = 0; j < SCH; j++) {
            iA[j][ch] = pa; iB[j][ch] = pb; iP[j][ch] = ppf;
            float ps = ppf + Lw;
            float dp = sP[j][ch];
            float d  = ps - dp;
            bool  ge = (d >= 0.f);
            float e  = __expf(ge ? -d : d);
            float e1 = ge ? 1.f : e;
            float e2 = ge ? e   : 1.f;
            pa  = pa * e1 + sA[j][ch] * e2;
            pb  = pb * e1 + sB[j][ch] * e2;
            ppf = ge ? ps : dp;
        }
    }
    __syncthreads();

    aa = iA[chunk][chan]; bb = iB[chunk][chan]; pp = iP[chunk][chan];
    __half* o = dir ? wb : wf;
    {
        int tm0 = dir ? (TT - 1 - s0) : s0;
        int dt  = dir ? -1 : 1;
        size_t off = base + (size_t)tm0 * CC;
        ptrdiff_t doff = (ptrdiff_t)dt * CC;
        #pragma unroll 4
        for (int t = 0; t < SLEN; ++t, off += doff) {
            float kk = __half2float(k[off]), vv = __half2float(v[off]);
            float uk = uu + kk;
            {
                float d  = pp - uk;
                bool  ge = (d >= 0.f);
                float e  = __expf(ge ? -d : d);
                float e1 = ge ? 1.f : e;
                float e2 = ge ? e   : 1.f;
                o[off] = __float2half_rn((e1 * aa + e2 * vv) / (e1 * bb + e2));
            }
            {
                float pw = pp + w;
                float d  = pw - kk;
                bool  ge = (d >= 0.f);
                float e  = __expf(ge ? -d : d);
                float f1 = ge ? 1.f : e;
                float f2 = ge ? e   : 1.f;
                aa = f1 * aa + f2 * vv;
                bb = f1 * bb + f2;
                pp = ge ? pw : kk;
            }
        }
    }
}

// mix: rh <- fp16(r * 0.5 * (wf + wb))
__global__ void mix_kernel(const __half* __restrict__ r,
                           const __half* __restrict__ wf,
                           const __half* __restrict__ wb,
                           __half* __restrict__ rh) {
    size_t i = ((size_t)blockIdx.x * blockDim.x + threadIdx.x) * 8;
    uint4 rv = *(const uint4*)(r + i);
    uint4 fv = *(const uint4*)(wf + i);
    uint4 bv = *(const uint4*)(wb + i);
    uint4 ov;
    const uint32_t* rp = &rv.x;
    const uint32_t* fp = &fv.x;
    const uint32_t* bp = &bv.x;
    uint32_t* op = &ov.x;
    #pragma unroll
    for (int j = 0; j < 4; j++) {
        float2 rr = __half22float2(*(const __half2*)&rp[j]);
        float2 ff = __half22float2(*(const __half2*)&fp[j]);
        float2 bbv = __half22float2(*(const __half2*)&bp[j]);
        __half2 h = __floats2half2_rn(rr.x * 0.5f * (ff.x + bbv.x),
                                      rr.y * 0.5f * (ff.y + bbv.y));
        op[j] = *(uint32_t*)&h;
    }
    *(uint4*)(rh + i) = ov;
}

// ---------------------------------------------------------------------------
// Launch
// ---------------------------------------------------------------------------
extern "C" void kernel_launch(void* const* d_in, const int* in_sizes, int n_in,
                              void* d_out, int out_size) {
    const float* x     = (const float*)d_in[0];
    const float* ln1w  = (const float*)d_in[1];
    const float* ln1b  = (const float*)d_in[2];
    const float* ln2w  = (const float*)d_in[3];
    const float* ln2b  = (const float*)d_in[4];
    const float* Wr    = (const float*)d_in[5];
    const float* Wk    = (const float*)d_in[6];
    const float* Wv    = (const float*)d_in[7];
    const float* Wo    = (const float*)d_in[8];
    const float* decay = (const float*)d_in[9];
    const float* u     = (const float*)d_in[10];
    const float* Wfk   = (const float*)d_in[11];
    const float* Wfv   = (const float*)d_in[12];
    const float* Wfr   = (const float*)d_in[13];
    float* out = (float*)d_out;

    __half *rs, *k, *v, *wf, *wb, *xnh, *rh, *kkh;
    __half *hWkv, *hWo, *hWffn, *hWfv;
    cudaGetSymbolAddress((void**)&rs,  g_rs);
    cudaGetSymbolAddress((void**)&k,   g_k);
    cudaGetSymbolAddress((void**)&v,   g_v);
    cudaGetSymbolAddress((void**)&wf,  g_wf);
    cudaGetSymbolAddress((void**)&wb,  g_wb);
    cudaGetSymbolAddress((void**)&xnh, g_xnh);
    cudaGetSymbolAddress((void**)&rh,  g_rh);
    cudaGetSymbolAddress((void**)&kkh, g_kkh);
    cudaGetSymbolAddress((void**)&hWkv,  g_wkv);
    cudaGetSymbolAddress((void**)&hWo,   g_wo);
    cudaGetSymbolAddress((void**)&hWffn, g_wffn);
    cudaGetSymbolAddress((void**)&hWfv,  g_wfv);

    const int smem = 2 * STG_BYTES + 256;  // 64KB + align pad
    cudaFuncSetAttribute(gemm_h<EPI_ADD>,  cudaFuncAttributeMaxDynamicSharedMemorySize, smem);
    cudaFuncSetAttribute(gemm_h<EPI_MADD>, cudaFuncAttributeMaxDynamicSharedMemorySize, smem);
    cudaFuncSetAttribute(gemm_h<EPI_RKV>,  cudaFuncAttributeMaxDynamicSharedMemorySize, smem);
    cudaFuncSetAttribute(gemm_h<EPI_FFN1>, cudaFuncAttributeMaxDynamicSharedMemorySize, smem);

    // persistent grids: min(tiles, 2*148)
    const int PG = 296;
    const int tRKV = (3*CC/128) * MTILES;     // 24*64 = 1536
    const int tC   = (CC/128)   * MTILES;     // 8*64  = 512
    const int tFFN = ((C4+CC)/128) * MTILES;  // 40*64 = 2560
    const int gRKV = PG, gC = PG, gFFN = PG;

    // 0) convert + pack all weights to fp16 in ONE launch
    cvt_all_kernel<<<13 * 128, 512>>>(Wr, Wk, Wv, Wo, Wfk, Wfv, Wfr,
                                      hWkv, hWo, hWffn, hWfv);
    // 1) ln1 -> fp16
    ln_kernel<<<MM, 256>>>(x, ln1w, ln1b, xnh);
    // 2) fused r|k|v projection -> fp16 r (sigmoid), k, v
    gemm_h<EPI_RKV><<<gRKV, 256, smem>>>(xnh, hWkv, nullptr, rs, k, v,
                                         nullptr, nullptr, CC, tRKV);
    // 3) bidirectional wkv scan (chunked two-pass, single-exp steps)
    scan2_kernel<<<dim3(CC / 32, BBATCH, 2), 512>>>(decay, u, k, v, wf, wb);
    // 4) rh = fp16(r * 0.5*(wf+wb))
    mix_kernel<<<(MM * CC) / 2048, 256>>>(rs, wf, wb, rh);
    // 5) out = x + (r*wkv) @ Wo^T
    gemm_h<EPI_ADD><<<gC, 256, smem>>>(rh, hWo, out, nullptr, nullptr, nullptr,
                                       x, nullptr, CC, tC);
    // 6) ln2 -> fp16
    ln_kernel<<<MM, 256>>>(out, ln2w, ln2b, xnh);
    // 7) fused ffn1: kk = fp16(relu^2), gate = fp16 sigmoid (into rs)
    gemm_h<EPI_FFN1><<<gFFN, 256, smem>>>(xnh, hWffn, nullptr, kkh, rs, nullptr,
                                          nullptr, nullptr, CC, tFFN);
    // 8) out += gate * (kk @ Wfv^T)
    gemm_h<EPI_MADD><<<gC, 256, smem>>>(kkh, hWfv, out, nullptr, nullptr, nullptr,
                                        out, rs, C4, tC);
}

// round 16
// speedup vs baseline: 1.0487x; 1.0487x over previous
#include <cuda_runtime.h>
#include <cuda_fp16.h>
#include <cstdint>
#include <cstddef>

// Problem constants
#define BBATCH 8
#define TT 1024
#define CC 1024
#define MM (BBATCH*TT)          // 8192 rows
#define C4 (4*CC)               // 4096
#define MEG (CC*CC)             // 1048576

// ---------------------------------------------------------------------------
// Scratch (static __device__ arrays; no allocation allowed)
// ---------------------------------------------------------------------------
__device__ __half g_rs [MM*CC];            // sigmoid(xn Wr^T); later ffn sigmoid gate
__device__ __half g_k  [MM*CC];
__device__ __half g_v  [MM*CC];
__device__ __half g_wf [MM*CC];
__device__ __half g_wb [MM*CC];
__device__ __half g_xnh[MM*CC];            // fp16 LN output (GEMM A)
__device__ __half g_rh [MM*CC];            // fp16 r*wkv (GEMM A)
__device__ __half g_kkh[(size_t)MM*C4];    // fp16 ffn hidden (GEMM A)
// packed fp16 weights (GEMM B, rows = output features, K contiguous)
__device__ __half g_wkv [(size_t)3*MEG];         // [Wr; Wk; Wv]
__device__ __half g_wo  [MEG];                   // Wo
__device__ __half g_wffn[(size_t)5*MEG];         // [Wfk; Wfr]
__device__ __half g_wfv [(size_t)4*MEG];         // Wfv

// ---------------------------------------------------------------------------
// PTX helpers
// ---------------------------------------------------------------------------
__device__ __forceinline__ void cp_async16(uint32_t sa, const void* gm) {
    asm volatile("cp.async.cg.shared.global [%0], [%1], 16;" :: "r"(sa), "l"(gm));
}
__device__ __forceinline__ void ldsm_x4(uint32_t* r, uint32_t addr) {
    asm volatile("ldmatrix.sync.aligned.m8n8.x4.shared.b16 {%0,%1,%2,%3}, [%4];"
                 : "=r"(r[0]), "=r"(r[1]), "=r"(r[2]), "=r"(r[3]) : "r"(addr));
}
__device__ __forceinline__ void mma_f16(float* c, const uint32_t* a, const uint32_t* b) {
    asm volatile(
        "mma.sync.aligned.m16n8k16.row.col.f32.f16.f16.f32 "
        "{%0,%1,%2,%3}, {%4,%5,%6,%7}, {%8,%9}, {%0,%1,%2,%3};"
        : "+f"(c[0]), "+f"(c[1]), "+f"(c[2]), "+f"(c[3])
        : "r"(a[0]), "r"(a[1]), "r"(a[2]), "r"(a[3]), "r"(b[0]), "r"(b[1]));
}
__device__ __forceinline__ uint32_t sw128(uint32_t off) {
    return off ^ ((off >> 3) & 0x70);
}
__device__ __forceinline__ float sigm(float x) { return 1.f / (1.f + __expf(-x)); }

// ---------------------------------------------------------------------------
// fp16 GEMM: out = epilogue( A[M,K] * B[N,K]^T ), accum f32
// CTA tile 128x128, BK=64 halves, 2-stage cp.async, 256 threads (8 warps),
// warp tile 64x32 — the measured optimum (rounds 9/11). NOT persistent.
// ---------------------------------------------------------------------------
#define EPI_ADD     0   // Cf = aux1 + acc                          (float out)
#define EPI_MADD    1   // Cf = aux1 + auxh * acc   (auxh fp16 gate, float out)
#define EPI_RKV     2   // region0: sigmoid->Ch ; region1: raw->h2 ; region2: raw->h3
#define EPI_FFN1    3   // col<4096: relu^2 -> Ch ; else: sigmoid -> h2

#define STG_BYTES 32768   // 16KB A (128x128B) + 16KB B

template <int EPI>
__global__ __launch_bounds__(256, 2)
void gemm_h(const __half* __restrict__ A, const __half* __restrict__ Bw,
            float* __restrict__ Cf, __half* __restrict__ Ch,
            __half* __restrict__ h2, __half* __restrict__ h3,
            const float* __restrict__ aux1, const __half* __restrict__ auxh,
            int K)
{
    extern __shared__ char smem_raw[];
    const uint32_t sb = ((uint32_t)__cvta_generic_to_shared(smem_raw) + 127u) & ~127u;

    const int tid  = threadIdx.x;
    const int warp = tid >> 5;
    const int lane = tid & 31;
    const int bm   = blockIdx.y * 128;
    const int bn   = blockIdx.x * 128;
    const int wm   = (warp & 1) * 64;
    const int wn   = (warp >> 1) * 32;
    const int nK   = K >> 6;            // K tiles of 64 halves

    const int rowA = lane & 15;
    const int kA   = (lane >> 4) << 3;
    const int rowB = (lane & 7) + ((lane >> 4) << 3);
    const int kB   = ((lane >> 3) & 1) << 3;

    float acc[4][4][4];
    #pragma unroll
    for (int mt = 0; mt < 4; mt++)
        #pragma unroll
        for (int nt = 0; nt < 4; nt++)
            #pragma unroll
            for (int i = 0; i < 4; i++) acc[mt][nt][i] = 0.f;

    auto load_tile = [&](int kt, int s) {
        const __half* Ag = A  + (size_t)bm * K + kt * 64;
        const __half* Bg = Bw + (size_t)bn * K + kt * 64;
        uint32_t sA = sb + s * STG_BYTES;
        uint32_t sB = sA + 16384;
        #pragma unroll
        for (int i = 0; i < 4; i++) {
            int n = tid + i * 256;
            int row = n >> 3, c = n & 7;
            uint32_t sw = sw128((uint32_t)(row * 128 + c * 16));
            cp_async16(sA + sw, Ag + (size_t)row * K + c * 8);
            cp_async16(sB + sw, Bg + (size_t)row * K + c * 8);
        }
    };

    load_tile(0, 0);
    asm volatile("cp.async.commit_group;");

    for (int t = 0; t < nK; t++) {
        if (t + 1 < nK) {
            load_tile(t + 1, (t + 1) & 1);
            asm volatile("cp.async.commit_group;");
            asm volatile("cp.async.wait_group 1;");
        } else {
            asm volatile("cp.async.wait_group 0;");
        }
        __syncthreads();

        uint32_t sA = sb + (t & 1) * STG_BYTES;
        uint32_t sB = sA + 16384;

        #pragma unroll
        for (int ks = 0; ks < 4; ks++) {
            uint32_t a[4][4], b[4][2];
            #pragma unroll
            for (int mt = 0; mt < 4; mt++) {
                int r = wm + mt * 16 + rowA;
                uint32_t off = (uint32_t)(r * 128 + (ks * 16 + kA) * 2);
                ldsm_x4(a[mt], sA + sw128(off));
            }
            #pragma unroll
            for (int nt2 = 0; nt2 < 2; nt2++) {
                uint32_t rb[4];
                int n = wn + nt2 * 16 + rowB;
                uint32_t off = (uint32_t)(n * 128 + (ks * 16 + kB) * 2);
                ldsm_x4(rb, sB + sw128(off));
                b[nt2 * 2][0]     = rb[0]; b[nt2 * 2][1]     = rb[1];
                b[nt2 * 2 + 1][0] = rb[2]; b[nt2 * 2 + 1][1] = rb[3];
            }
            #pragma unroll
            for (int mt = 0; mt < 4; mt++)
                #pragma unroll
                for (int nt = 0; nt < 4; nt++)
                    mma_f16(acc[mt][nt], a[mt], b[nt]);
        }
        __syncthreads();
    }

    const int g = lane >> 2, q = lane & 3;
    #pragma unroll
    for (int mt = 0; mt < 4; mt++) {
        #pragma unroll
        for (int hv = 0; hv < 2; hv++) {
            int row = bm + wm + mt * 16 + g + hv * 8;
            #pragma unroll
            for (int nt = 0; nt < 4; nt++) {
                int col = bn + wn + nt * 8 + q * 2;
                float c0 = acc[mt][nt][hv * 2];
                float c1 = acc[mt][nt][hv * 2 + 1];
                if (EPI == EPI_ADD) {
                    size_t gi = (size_t)row * CC + col;
                    float2 a2 = *(const float2*)(aux1 + gi);
                    *(float2*)(Cf + gi) = make_float2(a2.x + c0, a2.y + c1);
                } else if (EPI == EPI_MADD) {
                    size_t gi = (size_t)row * CC + col;
                    float2 a2 = *(const float2*)(aux1 + gi);
                    float2 s2 = __half22float2(*(const __half2*)(auxh + gi));
                    *(float2*)(Cf + gi) = make_float2(a2.x + s2.x * c0,
                                                      a2.y + s2.y * c1);
                } else if (EPI == EPI_RKV) {
                    int region = col >> 10;            // uniform per CTA
                    int lc = col & (CC - 1);
                    size_t gi = (size_t)row * CC + lc;
                    if (region == 0)
                        *(__half2*)(Ch + gi) = __floats2half2_rn(sigm(c0), sigm(c1));
                    else if (region == 1)
                        *(__half2*)(h2 + gi) = __floats2half2_rn(c0, c1);
                    else
                        *(__half2*)(h3 + gi) = __floats2half2_rn(c0, c1);
                } else { // EPI_FFN1
                    if (col < C4) {
                        float t0 = fmaxf(c0, 0.f), t1 = fmaxf(c1, 0.f);
                        *(__half2*)(Ch + (size_t)row * C4 + col) =
                            __floats2half2_rn(t0 * t0, t1 * t1);
                    } else {
                        size_t gi = (size_t)row * CC + (col - C4);
                        *(__half2*)(h2 + gi) = __floats2half2_rn(sigm(c0), sigm(c1));
                    }
                }
            }
        }
    }
}

// ---------------------------------------------------------------------------
// Single-launch weight conversion+packing — 16 elems/thread, 512 threads.
// ---------------------------------------------------------------------------
__global__ __launch_bounds__(512)
void cvt_all_kernel(const float* __restrict__ Wr,
                    const float* __restrict__ Wk,
                    const float* __restrict__ Wv,
                    const float* __restrict__ Wo,
                    const float* __restrict__ Wfk,
                    const float* __restrict__ Wfv,
                    const float* __restrict__ Wfr,
                    __half* __restrict__ wkv,
                    __half* __restrict__ wo,
                    __half* __restrict__ wffn,
                    __half* __restrict__ wfv) {
    const size_t i = ((size_t)blockIdx.x * 512 + threadIdx.x) * 16;
    const int region = blockIdx.x >> 7;           // 0..12, uniform per block
    const float* s; __half* d;
    if      (region < 1)  { s = Wr  + i;                     d = wkv  + i; }
    else if (region < 2)  { s = Wk  + (i - (size_t)MEG);     d = wkv  + i; }
    else if (region < 3)  { s = Wv  + (i - (size_t)2*MEG);   d = wkv  + i; }
    else if (region < 4)  { s = Wo  + (i - (size_t)3*MEG);   d = wo   + (i - (size_t)3*MEG); }
    else if (region < 8)  { s = Wfk + (i - (size_t)4*MEG);   d = wffn + (i - (size_t)4*MEG); }
    else if (region < 9)  { s = Wfr + (i - (size_t)8*MEG);   d = wffn + (i - (size_t)4*MEG); }
    else                  { s = Wfv + (i - (size_t)9*MEG);   d = wfv  + (i - (size_t)9*MEG); }
    #pragma unroll
    for (int h = 0; h < 2; h++) {
        float4 v0 = *(const float4*)(s + h * 8);
        float4 v1 = *(const float4*)(s + h * 8 + 4);
        __half2 h0 = __floats2half2_rn(v0.x, v0.y);
        __half2 h1 = __floats2half2_rn(v0.z, v0.w);
        __half2 h2 = __floats2half2_rn(v1.x, v1.y);
        __half2 h3 = __floats2half2_rn(v1.z, v1.w);
        uint4 pk;
        pk.x = *(uint32_t*)&h0; pk.y = *(uint32_t*)&h1;
        pk.z = *(uint32_t*)&h2; pk.w = *(uint32_t*)&h3;
        *(uint4*)(d + h * 8) = pk;
    }
}

// ---------------------------------------------------------------------------
// LayerNorm: one block per row (C=1024, 256 threads); fp16 output
// ---------------------------------------------------------------------------
__global__ void ln_kernel(const float* __restrict__ x,
                          const float* __restrict__ w,
                          const float* __restrict__ b,
                          __half* __restrict__ out) {
    int row = blockIdx.x;
    const float* xr = x + (size_t)row * CC;
    float s = 0.f, s2 = 0.f;
    float vals[4];
    #pragma unroll
    for (int i = 0; i < 4; i++) {
        float t = xr[threadIdx.x + i * 256];
        vals[i] = t;
        s += t; s2 += t * t;
    }
    #pragma unroll
    for (int o = 16; o; o >>= 1) {
        s  += __shfl_xor_sync(0xffffffffu, s,  o);
        s2 += __shfl_xor_sync(0xffffffffu, s2, o);
    }
    __shared__ float sh[34];
    int warp = threadIdx.x >> 5, lane = threadIdx.x & 31;
    if (lane == 0) { sh[warp] = s; sh[warp + 8] = s2; }
    __syncthreads();
    if (threadIdx.x < 32) {
        s  = (threadIdx.x < 8) ? sh[threadIdx.x]     : 0.f;
        s2 = (threadIdx.x < 8) ? sh[threadIdx.x + 8] : 0.f;
        #pragma unroll
        for (int o = 4; o; o >>= 1) {
            s  += __shfl_xor_sync(0xffffffffu, s,  o);
            s2 += __shfl_xor_sync(0xffffffffu, s2, o);
        }
        if (threadIdx.x == 0) {
            float mu  = s * (1.f / CC);
            float var = s2 * (1.f / CC) - mu * mu;
            sh[32] = mu;
            sh[33] = rsqrtf(var + 1e-5f);
        }
    }
    __syncthreads();
    float mu = sh[32], rs = sh[33];
    __half* orow = out + (size_t)row * CC;
    #pragma unroll
    for (int i = 0; i < 4; i++) {
        int col = threadIdx.x + i * 256;
        orow[col] = __float2half_rn((vals[i] - mu) * rs * w[col] + b[col]);
    }
}

// ---------------------------------------------------------------------------
// Chunked two-pass WKV scan — 2 channels per thread via __half2 loads.
// Two independent recurrence chains per thread fill each other's MUFU/FFMA
// latency; warp loads are full 128B lines. Per-channel math bit-identical.
// Block: 512 thr = 16 chunks x 32 lanes; lane covers channels {2L, 2L+1}
// of a 64-channel group. Grid: (CC/64, BBATCH, 2) = 256 blocks.
// ---------------------------------------------------------------------------
#define SCH 16
#define SLEN 64

__global__ __launch_bounds__(512)
void scan2_kernel(const float* __restrict__ decay,
                  const float* __restrict__ u,
                  const __half* __restrict__ k,
                  const __half* __restrict__ v,
                  __half* __restrict__ wf,
                  __half* __restrict__ wb) {
    __shared__ float2 sA[SCH][32], sB[SCH][32], sP[SCH][32];
    __shared__ float2 iA[SCH][32], iB[SCH][32], iP[SCH][32];

    const int lane2 = threadIdx.x & 31;           // channel-pair index
    const int chunk = threadIdx.x >> 5;
    const int c0    = blockIdx.x * 64 + lane2 * 2;
    const int b     = blockIdx.y;
    const int dir   = blockIdx.z;

    const float2 dec = *(const float2*)(decay + c0);
    const float2 uu  = *(const float2*)(u + c0);
    const float wx = -__expf(dec.x);
    const float wy = -__expf(dec.y);
    const size_t base = (size_t)b * TT * CC + c0;   // element offset (even)
    const int s0 = chunk * SLEN;

    float ax = 0.f, bx = 0.f, px = -1e38f;
    float ay = 0.f, by = 0.f, py = -1e38f;
    {
        int tm0 = dir ? (TT - 1 - s0) : s0;
        int dt  = dir ? -1 : 1;
        size_t off = base + (size_t)tm0 * CC;
        ptrdiff_t doff = (ptrdiff_t)dt * CC;
        #pragma unroll 4
        for (int t = 0; t < SLEN; ++t, off += doff) {
            float2 kk = __half22float2(*(const __half2*)(k + off));
            float2 vv = __half22float2(*(const __half2*)(v + off));
            {   // chain x
                float pw = px + wx;
                float d  = pw - kk.x;
                bool  ge = (d >= 0.f);
                float e  = __expf(ge ? -d : d);
                float f1 = ge ? 1.f : e;
                float f2 = ge ? e   : 1.f;
                ax = f1 * ax + f2 * vv.x;
                bx = f1 * bx + f2;
                px = ge ? pw : kk.x;
            }
            {   // chain y
                float pw = py + wy;
                float d  = pw - kk.y;
                bool  ge = (d >= 0.f);
                float e  = __expf(ge ? -d : d);
                float f1 = ge ? 1.f : e;
                float f2 = ge ? e   : 1.f;
                ay = f1 * ay + f2 * vv.y;
                by = f1 * by + f2;
                py = ge ? pw : kk.y;
            }
        }
    }
    sA[chunk][lane2] = make_float2(ax, ay);
    sB[chunk][lane2] = make_float2(bx, by);
    sP[chunk][lane2] = make_float2(px, py);
    __syncthreads();

    if (threadIdx.x < 32) {
        const int ch = threadIdx.x;
        float pax = 0.f, pbx = 0.f, ppx = -1e38f;
        float pay = 0.f, pby = 0.f, ppy = -1e38f;
        float2 decl = *(const float2*)(decay + blockIdx.x * 64 + ch * 2);
        const float lwx = SLEN * (-__expf(decl.x));
        const float lwy = SLEN * (-__expf(decl.y));
        #pragma unroll
        for (int j = 0; j < SCH; j++) {
            iA[j][ch] = make_float2(pax, pay);
            iB[j][ch] = make_float2(pbx, pby);
            iP[j][ch] = make_float2(ppx, ppy);
            float2 dA = sA[j][ch], dB = sB[j][ch], dP = sP[j][ch];
            {
                float ps = ppx + lwx;
                float d  = ps - dP.x;
                bool  ge = (d >= 0.f);
                float e  = __expf(ge ? -d : d);
                float e1 = ge ? 1.f : e;
                float e2 = ge ? e   : 1.f;
                pax = pax * e1 + dA.x * e2;
                pbx = pbx * e1 + dB.x * e2;
                ppx = ge ? ps : dP.x;
            }
            {
                float ps = ppy + lwy;
                float d  = ps - dP.y;
                bool  ge = (d >= 0.f);
                float e  = __expf(ge ? -d : d);
                float e1 = ge ? 1.f : e;
                float e2 = ge ? e   : 1.f;
                pay = pay * e1 + dA.y * e2;
                pby = pby * e1 + dB.y * e2;
                ppy = ge ? ps : dP.y;
            }
        }
    }
    __syncthreads();

    {
        float2 t;
        t = iA[chunk][lane2]; ax = t.x; ay = t.y;
        t = iB[chunk][lane2]; bx = t.x; by = t.y;
        t = iP[chunk][lane2]; px = t.x; py = t.y;
    }
    __half* o = dir ? wb : wf;
    {
        int tm0 = dir ? (TT - 1 - s0) : s0;
        int dt  = dir ? -1 : 1;
        size_t off = base + (size_t)tm0 * CC;
        ptrdiff_t doff = (ptrdiff_t)dt * CC;
        #pragma unroll 4
        for (int t = 0; t < SLEN; ++t, off += doff) {
            float2 kk = __half22float2(*(const __half2*)(k + off));
            float2 vv = __half22float2(*(const __half2*)(v + off));
            float ox, oy;
            {   // output combine x
                float uk = uu.x + kk.x;
                float d  = px - uk;
                bool  ge = (d >= 0.f);
                float e  = __expf(ge ? -d : d);
                float e1 = ge ? 1.f : e;
                float e2 = ge ? e   : 1.f;
                ox = (e1 * ax + e2 * vv.x) / (e1 * bx + e2);
            }
            {   // output combine y
                float uk = uu.y + kk.y;
                float d  = py - uk;
                bool  ge = (d >= 0.f);
                float e  = __expf(ge ? -d : d);
                float e1 = ge ? 1.f : e;
                float e2 = ge ? e   : 1.f;
                oy = (e1 * ay + e2 * vv.y) / (e1 * by + e2);
            }
            *(__half2*)(o + off) = __floats2half2_rn(ox, oy);
            {   // state update x
                float pw = px + wx;
                float d  = pw - kk.x;
                bool  ge = (d >= 0.f);
                float e  = __expf(ge ? -d : d);
                float f1 = ge ? 1.f : e;
                float f2 = ge ? e   : 1.f;
                ax = f1 * ax + f2 * vv.x;
                bx = f1 * bx + f2;
                px = ge ? pw : kk.x;
            }
            {   // state update y
                float pw = py + wy;
                float d  = pw - kk.y;
                bool  ge = (d >= 0.f);
                float e  = __expf(ge ? -d : d);
                float f1 = ge ? 1.f : e;
                float f2 = ge ? e   : 1.f;
                ay = f1 * ay + f2 * vv.y;
                by = f1 * by + f2;
                py = ge ? pw : kk.y;
            }
        }
    }
}

// mix: rh <- fp16(r * 0.5 * (wf + wb))
__global__ void mix_kernel(const __half* __restrict__ r,
                           const __half* __restrict__ wf,
                           const __half* __restrict__ wb,
                           __half* __restrict__ rh) {
    size_t i = ((size_t)blockIdx.x * blockDim.x + threadIdx.x) * 8;
    uint4 rv = *(const uint4*)(r + i);
    uint4 fv = *(const uint4*)(wf + i);
    uint4 bv = *(const uint4*)(wb + i);
    uint4 ov;
    const uint32_t* rp = &rv.x;
    const uint32_t* fp = &fv.x;
    const uint32_t* bp = &bv.x;
    uint32_t* op = &ov.x;
    #pragma unroll
    for (int j = 0; j < 4; j++) {
        float2 rr = __half22float2(*(const __half2*)&rp[j]);
        float2 ff = __half22float2(*(const __half2*)&fp[j]);
        float2 bbv = __half22float2(*(const __half2*)&bp[j]);
        __half2 h = __floats2half2_rn(rr.x * 0.5f * (ff.x + bbv.x),
                                      rr.y * 0.5f * (ff.y + bbv.y));
        op[j] = *(uint32_t*)&h;
    }
    *(uint4*)(rh + i) = ov;
}

// ---------------------------------------------------------------------------
// Launch
// ---------------------------------------------------------------------------
extern "C" void kernel_launch(void* const* d_in, const int* in_sizes, int n_in,
                              void* d_out, int out_size) {
    const float* x     = (const float*)d_in[0];
    const float* ln1w  = (const float*)d_in[1];
    const float* ln1b  = (const float*)d_in[2];
    const float* ln2w  = (const float*)d_in[3];
    const float* ln2b  = (const float*)d_in[4];
    const float* Wr    = (const float*)d_in[5];
    const float* Wk    = (const float*)d_in[6];
    const float* Wv    = (const float*)d_in[7];
    const float* Wo    = (const float*)d_in[8];
    const float* decay = (const float*)d_in[9];
    const float* u     = (const float*)d_in[10];
    const float* Wfk   = (const float*)d_in[11];
    const float* Wfv   = (const float*)d_in[12];
    const float* Wfr   = (const float*)d_in[13];
    float* out = (float*)d_out;

    __half *rs, *k, *v, *wf, *wb, *xnh, *rh, *kkh;
    __half *hWkv, *hWo, *hWffn, *hWfv;
    cudaGetSymbolAddress((void**)&rs,  g_rs);
    cudaGetSymbolAddress((void**)&k,   g_k);
    cudaGetSymbolAddress((void**)&v,   g_v);
    cudaGetSymbolAddress((void**)&wf,  g_wf);
    cudaGetSymbolAddress((void**)&wb,  g_wb);
    cudaGetSymbolAddress((void**)&xnh, g_xnh);
    cudaGetSymbolAddress((void**)&rh,  g_rh);
    cudaGetSymbolAddress((void**)&kkh, g_kkh);
    cudaGetSymbolAddress((void**)&hWkv,  g_wkv);
    cudaGetSymbolAddress((void**)&hWo,   g_wo);
    cudaGetSymbolAddress((void**)&hWffn, g_wffn);
    cudaGetSymbolAddress((void**)&hWfv,  g_wfv);

    const int smem = 2 * STG_BYTES + 256;  // 64KB + align pad
    cudaFuncSetAttribute(gemm_h<EPI_ADD>,  cudaFuncAttributeMaxDynamicSharedMemorySize, smem);
    cudaFuncSetAttribute(gemm_h<EPI_MADD>, cudaFuncAttributeMaxDynamicSharedMemorySize, smem);
    cudaFuncSetAttribute(gemm_h<EPI_RKV>,  cudaFuncAttributeMaxDynamicSharedMemorySize, smem);
    cudaFuncSetAttribute(gemm_h<EPI_FFN1>, cudaFuncAttributeMaxDynamicSharedMemorySize, smem);

    dim3 gRKV (3*CC / 128, MM / 128);   // (24, 64)
    dim3 gC   (CC / 128,   MM / 128);   // (8, 64)
    dim3 gFFN ((C4+CC)/128, MM / 128);  // (40, 64)

    // 0) convert + pack all weights to fp16 in ONE launch
    cvt_all_kernel<<<13 * 128, 512>>>(Wr, Wk, Wv, Wo, Wfk, Wfv, Wfr,
                                      hWkv, hWo, hWffn, hWfv);
    // 1) ln1 -> fp16
    ln_kernel<<<MM, 256>>>(x, ln1w, ln1b, xnh);
    // 2) fused r|k|v projection -> fp16 r (sigmoid), k, v
    gemm_h<EPI_RKV><<<gRKV, 256, smem>>>(xnh, hWkv, nullptr, rs, k, v,
                                         nullptr, nullptr, CC);
    // 3) bidirectional wkv scan (chunked two-pass, 2 channels/thread)
    scan2_kernel<<<dim3(CC / 64, BBATCH, 2), 512>>>(decay, u, k, v, wf, wb);
    // 4) rh = fp16(r * 0.5*(wf+wb))
    mix_kernel<<<(MM * CC) / 2048, 256>>>(rs, wf, wb, rh);
    // 5) out = x + (r*wkv) @ Wo^T
    gemm_h<EPI_ADD><<<gC, 256, smem>>>(rh, hWo, out, nullptr, nullptr, nullptr,
                                       x, nullptr, CC);
    // 6) ln2 -> fp16
    ln_kernel<<<MM, 256>>>(out, ln2w, ln2b, xnh);
    // 7) fused ffn1: kk = fp16(relu^2), gate = fp16 sigmoid (into rs)
    gemm_h<EPI_FFN1><<<gFFN, 256, smem>>>(xnh, hWffn, nullptr, kkh, rs, nullptr,
                                          nullptr, nullptr, CC);
    // 8) out += gate * (kk @ Wfv^T)
    gemm_h<EPI_MADD><<<gC, 256, smem>>>(kkh, hWfv, out, nullptr, nullptr, nullptr,
                                        out, rs, C4);
}

// round 17
// speedup vs baseline: 1.0553x; 1.0063x over previous
#include <cuda_runtime.h>
#include <cuda_fp16.h>
#include <cstdint>
#include <cstddef>

// Problem constants
#define BBATCH 8
#define TT 1024
#define CC 1024
#define MM (BBATCH*TT)          // 8192 rows
#define C4 (4*CC)               // 4096
#define MEG (CC*CC)             // 1048576

// ---------------------------------------------------------------------------
// Scratch (static __device__ arrays; no allocation allowed)
// ---------------------------------------------------------------------------
__device__ __half g_rs [MM*CC];            // sigmoid(xn Wr^T); later ffn sigmoid gate
__device__ __half g_k  [MM*CC];
__device__ __half g_v  [MM*CC];
__device__ __half g_wf [MM*CC];
__device__ __half g_wb [MM*CC];
__device__ __half g_xnh[MM*CC];            // fp16 LN output (GEMM A)
__device__ __half g_rh [MM*CC];            // fp16 r*wkv (GEMM A)
__device__ __half g_kkh[(size_t)MM*C4];    // fp16 ffn hidden (GEMM A)
// packed fp16 weights (GEMM B, rows = output features, K contiguous)
__device__ __half g_wkv [(size_t)3*MEG];         // [Wr; Wk; Wv]
__device__ __half g_wo  [MEG];                   // Wo
__device__ __half g_wffn[(size_t)5*MEG];         // [Wfk; Wfr]
__device__ __half g_wfv [(size_t)4*MEG];         // Wfv

// ---------------------------------------------------------------------------
// PTX helpers
// ---------------------------------------------------------------------------
__device__ __forceinline__ void cp_async16(uint32_t sa, const void* gm) {
    asm volatile("cp.async.cg.shared.global [%0], [%1], 16;" :: "r"(sa), "l"(gm));
}
__device__ __forceinline__ void ldsm_x4(uint32_t* r, uint32_t addr) {
    asm volatile("ldmatrix.sync.aligned.m8n8.x4.shared.b16 {%0,%1,%2,%3}, [%4];"
                 : "=r"(r[0]), "=r"(r[1]), "=r"(r[2]), "=r"(r[3]) : "r"(addr));
}
__device__ __forceinline__ void mma_f16(float* c, const uint32_t* a, const uint32_t* b) {
    asm volatile(
        "mma.sync.aligned.m16n8k16.row.col.f32.f16.f16.f32 "
        "{%0,%1,%2,%3}, {%4,%5,%6,%7}, {%8,%9}, {%0,%1,%2,%3};"
        : "+f"(c[0]), "+f"(c[1]), "+f"(c[2]), "+f"(c[3])
        : "r"(a[0]), "r"(a[1]), "r"(a[2]), "r"(a[3]), "r"(b[0]), "r"(b[1]));
}
__device__ __forceinline__ uint32_t sw128(uint32_t off) {
    return off ^ ((off >> 3) & 0x70);
}
__device__ __forceinline__ float sigm(float x) { return 1.f / (1.f + __expf(-x)); }

// ---------------------------------------------------------------------------
// fp16 GEMM: out = epilogue( A[M,K] * B[N,K]^T ), accum f32
// CTA tile 128x128, BK=64 halves, 2-stage cp.async, 256 threads (8 warps),
// warp tile 64x32 — measured-optimal shape. Single __syncthreads per K-iter:
// the barrier at iteration top both (a) makes all warps' cp.asyncs for tile t
// visible (each warp waited its own group first) and (b) guarantees everyone
// finished reading stage (t+1)&1 in iter t-1 before we overwrite it — because
// the next tile's loads are issued AFTER the barrier.
// ---------------------------------------------------------------------------
#define EPI_ADD     0   // Cf = aux1 + acc                          (float out)
#define EPI_MADD    1   // Cf = aux1 + auxh * acc   (auxh fp16 gate, float out)
#define EPI_RKV     2   // region0: sigmoid->Ch ; region1: raw->h2 ; region2: raw->h3
#define EPI_FFN1    3   // col<4096: relu^2 -> Ch ; else: sigmoid -> h2

#define STG_BYTES 32768   // 16KB A (128x128B) + 16KB B

template <int EPI>
__global__ __launch_bounds__(256, 2)
void gemm_h(const __half* __restrict__ A, const __half* __restrict__ Bw,
            float* __restrict__ Cf, __half* __restrict__ Ch,
            __half* __restrict__ h2, __half* __restrict__ h3,
            const float* __restrict__ aux1, const __half* __restrict__ auxh,
            int K)
{
    extern __shared__ char smem_raw[];
    const uint32_t sb = ((uint32_t)__cvta_generic_to_shared(smem_raw) + 127u) & ~127u;

    const int tid  = threadIdx.x;
    const int warp = tid >> 5;
    const int lane = tid & 31;
    const int bm   = blockIdx.y * 128;
    const int bn   = blockIdx.x * 128;
    const int wm   = (warp & 1) * 64;
    const int wn   = (warp >> 1) * 32;
    const int nK   = K >> 6;            // K tiles of 64 halves

    const int rowA = lane & 15;
    const int kA   = (lane >> 4) << 3;
    const int rowB = (lane & 7) + ((lane >> 4) << 3);
    const int kB   = ((lane >> 3) & 1) << 3;

    float acc[4][4][4];
    #pragma unroll
    for (int mt = 0; mt < 4; mt++)
        #pragma unroll
        for (int nt = 0; nt < 4; nt++)
            #pragma unroll
            for (int i = 0; i < 4; i++) acc[mt][nt][i] = 0.f;

    auto load_tile = [&](int kt, int s) {
        const __half* Ag = A  + (size_t)bm * K + kt * 64;
        const __half* Bg = Bw + (size_t)bn * K + kt * 64;
        uint32_t sA = sb + s * STG_BYTES;
        uint32_t sB = sA + 16384;
        #pragma unroll
        for (int i = 0; i < 4; i++) {
            int n = tid + i * 256;
            int row = n >> 3, c = n & 7;
            uint32_t sw = sw128((uint32_t)(row * 128 + c * 16));
            cp_async16(sA + sw, Ag + (size_t)row * K + c * 8);
            cp_async16(sB + sw, Bg + (size_t)row * K + c * 8);
        }
    };

    load_tile(0, 0);
    asm volatile("cp.async.commit_group;");

    for (int t = 0; t < nK; t++) {
        asm volatile("cp.async.wait_group 0;");   // my part of tile t landed
        __syncthreads();                          // all parts visible; stage
                                                  // (t+1)&1 free to overwrite
        if (t + 1 < nK) {
            load_tile(t + 1, (t + 1) & 1);
            asm volatile("cp.async.commit_group;");
        }

        uint32_t sA = sb + (t & 1) * STG_BYTES;
        uint32_t sB = sA + 16384;

        #pragma unroll
        for (int ks = 0; ks < 4; ks++) {
            uint32_t a[4][4], b[4][2];
            #pragma unroll
            for (int mt = 0; mt < 4; mt++) {
                int r = wm + mt * 16 + rowA;
                uint32_t off = (uint32_t)(r * 128 + (ks * 16 + kA) * 2);
                ldsm_x4(a[mt], sA + sw128(off));
            }
            #pragma unroll
            for (int nt2 = 0; nt2 < 2; nt2++) {
                uint32_t rb[4];
                int n = wn + nt2 * 16 + rowB;
                uint32_t off = (uint32_t)(n * 128 + (ks * 16 + kB) * 2);
                ldsm_x4(rb, sB + sw128(off));
                b[nt2 * 2][0]     = rb[0]; b[nt2 * 2][1]     = rb[1];
                b[nt2 * 2 + 1][0] = rb[2]; b[nt2 * 2 + 1][1] = rb[3];
            }
            #pragma unroll
            for (int mt = 0; mt < 4; mt++)
                #pragma unroll
                for (int nt = 0; nt < 4; nt++)
                    mma_f16(acc[mt][nt], a[mt], b[nt]);
        }
        // no second barrier: epilogue is register-only, and next iteration's
        // loads are gated by the top-of-loop barrier.
    }

    const int g = lane >> 2, q = lane & 3;
    #pragma unroll
    for (int mt = 0; mt < 4; mt++) {
        #pragma unroll
        for (int hv = 0; hv < 2; hv++) {
            int row = bm + wm + mt * 16 + g + hv * 8;
            #pragma unroll
            for (int nt = 0; nt < 4; nt++) {
                int col = bn + wn + nt * 8 + q * 2;
                float c0 = acc[mt][nt][hv * 2];
                float c1 = acc[mt][nt][hv * 2 + 1];
                if (EPI == EPI_ADD) {
                    size_t gi = (size_t)row * CC + col;
                    float2 a2 = *(const float2*)(aux1 + gi);
                    *(float2*)(Cf + gi) = make_float2(a2.x + c0, a2.y + c1);
                } else if (EPI == EPI_MADD) {
                    size_t gi = (size_t)row * CC + col;
                    float2 a2 = *(const float2*)(aux1 + gi);
                    float2 s2 = __half22float2(*(const __half2*)(auxh + gi));
                    *(float2*)(Cf + gi) = make_float2(a2.x + s2.x * c0,
                                                      a2.y + s2.y * c1);
                } else if (EPI == EPI_RKV) {
                    int region = col >> 10;            // uniform per CTA
                    int lc = col & (CC - 1);
                    size_t gi = (size_t)row * CC + lc;
                    if (region == 0)
                        *(__half2*)(Ch + gi) = __floats2half2_rn(sigm(c0), sigm(c1));
                    else if (region == 1)
                        *(__half2*)(h2 + gi) = __floats2half2_rn(c0, c1);
                    else
                        *(__half2*)(h3 + gi) = __floats2half2_rn(c0, c1);
                } else { // EPI_FFN1
                    if (col < C4) {
                        float t0 = fmaxf(c0, 0.f), t1 = fmaxf(c1, 0.f);
                        *(__half2*)(Ch + (size_t)row * C4 + col) =
                            __floats2half2_rn(t0 * t0, t1 * t1);
                    } else {
                        size_t gi = (size_t)row * CC + (col - C4);
                        *(__half2*)(h2 + gi) = __floats2half2_rn(sigm(c0), sigm(c1));
                    }
                }
            }
        }
    }
}

// ---------------------------------------------------------------------------
// Single-launch weight conversion+packing — 16 elems/thread, 512 threads.
// ---------------------------------------------------------------------------
__global__ __launch_bounds__(512)
void cvt_all_kernel(const float* __restrict__ Wr,
                    const float* __restrict__ Wk,
                    const float* __restrict__ Wv,
                    const float* __restrict__ Wo,
                    const float* __restrict__ Wfk,
                    const float* __restrict__ Wfv,
                    const float* __restrict__ Wfr,
                    __half* __restrict__ wkv,
                    __half* __restrict__ wo,
                    __half* __restrict__ wffn,
                    __half* __restrict__ wfv) {
    const size_t i = ((size_t)blockIdx.x * 512 + threadIdx.x) * 16;
    const int region = blockIdx.x >> 7;           // 0..12, uniform per block
    const float* s; __half* d;
    if      (region < 1)  { s = Wr  + i;                     d = wkv  + i; }
    else if (region < 2)  { s = Wk  + (i - (size_t)MEG);     d = wkv  + i; }
    else if (region < 3)  { s = Wv  + (i - (size_t)2*MEG);   d = wkv  + i; }
    else if (region < 4)  { s = Wo  + (i - (size_t)3*MEG);   d = wo   + (i - (size_t)3*MEG); }
    else if (region < 8)  { s = Wfk + (i - (size_t)4*MEG);   d = wffn + (i - (size_t)4*MEG); }
    else if (region < 9)  { s = Wfr + (i - (size_t)8*MEG);   d = wffn + (i - (size_t)4*MEG); }
    else                  { s = Wfv + (i - (size_t)9*MEG);   d = wfv  + (i - (size_t)9*MEG); }
    #pragma unroll
    for (int h = 0; h < 2; h++) {
        float4 v0 = *(const float4*)(s + h * 8);
        float4 v1 = *(const float4*)(s + h * 8 + 4);
        __half2 h0 = __floats2half2_rn(v0.x, v0.y);
        __half2 h1 = __floats2half2_rn(v0.z, v0.w);
        __half2 h2 = __floats2half2_rn(v1.x, v1.y);
        __half2 h3 = __floats2half2_rn(v1.z, v1.w);
        uint4 pk;
        pk.x = *(uint32_t*)&h0; pk.y = *(uint32_t*)&h1;
        pk.z = *(uint32_t*)&h2; pk.w = *(uint32_t*)&h3;
        *(uint4*)(d + h * 8) = pk;
    }
}

// ---------------------------------------------------------------------------
// LayerNorm: one block per row (C=1024, 256 threads); fp16 output
// ---------------------------------------------------------------------------
__global__ void ln_kernel(const float* __restrict__ x,
                          const float* __restrict__ w,
                          const float* __restrict__ b,
                          __half* __restrict__ out) {
    int row = blockIdx.x;
    const float* xr = x + (size_t)row * CC;
    float s = 0.f, s2 = 0.f;
    float vals[4];
    #pragma unroll
    for (int i = 0; i < 4; i++) {
        float t = xr[threadIdx.x + i * 256];
        vals[i] = t;
        s += t; s2 += t * t;
    }
    #pragma unroll
    for (int o = 16; o; o >>= 1) {
        s  += __shfl_xor_sync(0xffffffffu, s,  o);
        s2 += __shfl_xor_sync(0xffffffffu, s2, o);
    }
    __shared__ float sh[34];
    int warp = threadIdx.x >> 5, lane = threadIdx.x & 31;
    if (lane == 0) { sh[warp] = s; sh[warp + 8] = s2; }
    __syncthreads();
    if (threadIdx.x < 32) {
        s  = (threadIdx.x < 8) ? sh[threadIdx.x]     : 0.f;
        s2 = (threadIdx.x < 8) ? sh[threadIdx.x + 8] : 0.f;
        #pragma unroll
        for (int o = 4; o; o >>= 1) {
            s  += __shfl_xor_sync(0xffffffffu, s,  o);
            s2 += __shfl_xor_sync(0xffffffffu, s2, o);
        }
        if (threadIdx.x == 0) {
            float mu  = s * (1.f / CC);
            float var = s2 * (1.f / CC) - mu * mu;
            sh[32] = mu;
            sh[33] = rsqrtf(var + 1e-5f);
        }
    }
    __syncthreads();
    float mu = sh[32], rs = sh[33];
    __half* orow = out + (size_t)row * CC;
    #pragma unroll
    for (int i = 0; i < 4; i++) {
        int col = threadIdx.x + i * 256;
        orow[col] = __float2half_rn((vals[i] - mu) * rs * w[col] + b[col]);
    }
}

// ---------------------------------------------------------------------------
// Chunked two-pass WKV scan — 2 channels/thread, fp16 I/O, single-exp steps
// (round-16 version — measured 59us; at its floor, unchanged)
// ---------------------------------------------------------------------------
#define SCH 16
#define SLEN 64

__global__ __launch_bounds__(512)
void scan2_kernel(const float* __restrict__ decay,
                  const float* __restrict__ u,
                  const __half* __restrict__ k,
                  const __half* __restrict__ v,
                  __half* __restrict__ wf,
                  __half* __restrict__ wb) {
    __shared__ float2 sA[SCH][32], sB[SCH][32], sP[SCH][32];
    __shared__ float2 iA[SCH][32], iB[SCH][32], iP[SCH][32];

    const int lane2 = threadIdx.x & 31;           // channel-pair index
    const int chunk = threadIdx.x >> 5;
    const int c0    = blockIdx.x * 64 + lane2 * 2;
    const int b     = blockIdx.y;
    const int dir   = blockIdx.z;

    const float2 dec = *(const float2*)(decay + c0);
    const float2 uu  = *(const float2*)(u + c0);
    const float wx = -__expf(dec.x);
    const float wy = -__expf(dec.y);
    const size_t base = (size_t)b * TT * CC + c0;
    const int s0 = chunk * SLEN;

    float ax = 0.f, bx = 0.f, px = -1e38f;
    float ay = 0.f, by = 0.f, py = -1e38f;
    {
        int tm0 = dir ? (TT - 1 - s0) : s0;
        int dt  = dir ? -1 : 1;
        size_t off = base + (size_t)tm0 * CC;
        ptrdiff_t doff = (ptrdiff_t)dt * CC;
        #pragma unroll 4
        for (int t = 0; t < SLEN; ++t, off += doff) {
            float2 kk = __half22float2(*(const __half2*)(k + off));
            float2 vv = __half22float2(*(const __half2*)(v + off));
            {   // chain x
                float pw = px + wx;
                float d  = pw - kk.x;
                bool  ge = (d >= 0.f);
                float e  = __expf(ge ? -d : d);
                float f1 = ge ? 1.f : e;
                float f2 = ge ? e   : 1.f;
                ax = f1 * ax + f2 * vv.x;
                bx = f1 * bx + f2;
                px = ge ? pw : kk.x;
            }
            {   // chain y
                float pw = py + wy;
                float d  = pw - kk.y;
                bool  ge = (d >= 0.f);
                float e  = __expf(ge ? -d : d);
                float f1 = ge ? 1.f : e;
                float f2 = ge ? e   : 1.f;
                ay = f1 * ay + f2 * vv.y;
                by = f1 * by + f2;
                py = ge ? pw : kk.y;
            }
        }
    }
    sA[chunk][lane2] = make_float2(ax, ay);
    sB[chunk][lane2] = make_float2(bx, by);
    sP[chunk][lane2] = make_float2(px, py);
    __syncthreads();

    if (threadIdx.x < 32) {
        const int ch = threadIdx.x;
        float pax = 0.f, pbx = 0.f, ppx = -1e38f;
        float pay = 0.f, pby = 0.f, ppy = -1e38f;
        float2 decl = *(const float2*)(decay + blockIdx.x * 64 + ch * 2);
        const float lwx = SLEN * (-__expf(decl.x));
        const float lwy = SLEN * (-__expf(decl.y));
        #pragma unroll
        for (int j = 0; j < SCH; j++) {
            iA[j][ch] = make_float2(pax, pay);
            iB[j][ch] = make_float2(pbx, pby);
            iP[j][ch] = make_float2(ppx, ppy);
            float2 dA = sA[j][ch], dB = sB[j][ch], dP = sP[j][ch];
            {
                float ps = ppx + lwx;
                float d  = ps - dP.x;
                bool  ge = (d >= 0.f);
                float e  = __expf(ge ? -d : d);
                float e1 = ge ? 1.f : e;
                float e2 = ge ? e   : 1.f;
                pax = pax * e1 + dA.x * e2;
                pbx = pbx * e1 + dB.x * e2;
                ppx = ge ? ps : dP.x;
            }
            {
                float ps = ppy + lwy;
                float d  = ps - dP.y;
                bool  ge = (d >= 0.f);
                float e  = __expf(ge ? -d : d);
                float e1 = ge ? 1.f : e;
                float e2 = ge ? e   : 1.f;
                pay = pay * e1 + dA.y * e2;
                pby = pby * e1 + dB.y * e2;
                ppy = ge ? ps : dP.y;
            }
        }
    }
    __syncthreads();

    {
        float2 t;
        t = iA[chunk][lane2]; ax = t.x; ay = t.y;
        t = iB[chunk][lane2]; bx = t.x; by = t.y;
        t = iP[chunk][lane2]; px = t.x; py = t.y;
    }
    __half* o = dir ? wb : wf;
    {
        int tm0 = dir ? (TT - 1 - s0) : s0;
        int dt  = dir ? -1 : 1;
        size_t off = base + (size_t)tm0 * CC;
        ptrdiff_t doff = (ptrdiff_t)dt * CC;
        #pragma unroll 4
        for (int t = 0; t < SLEN; ++t, off += doff) {
            float2 kk = __half22float2(*(const __half2*)(k + off));
            float2 vv = __half22float2(*(const __half2*)(v + off));
            float ox, oy;
            {   // output combine x
                float uk = uu.x + kk.x;
                float d  = px - uk;
                bool  ge = (d >= 0.f);
                float e  = __expf(ge ? -d : d);
                float e1 = ge ? 1.f : e;
                float e2 = ge ? e   : 1.f;
                ox = (e1 * ax + e2 * vv.x) / (e1 * bx + e2);
            }
            {   // output combine y
                float uk = uu.y + kk.y;
                float d  = py - uk;
                bool  ge = (d >= 0.f);
                float e  = __expf(ge ? -d : d);
                float e1 = ge ? 1.f : e;
                float e2 = ge ? e   : 1.f;
                oy = (e1 * ay + e2 * vv.y) / (e1 * by + e2);
            }
            *(__half2*)(o + off) = __floats2half2_rn(ox, oy);
            {   // state update x
                float pw = px + wx;
                float d  = pw - kk.x;
                bool  ge = (d >= 0.f);
                float e  = __expf(ge ? -d : d);
                float f1 = ge ? 1.f : e;
                float f2 = ge ? e   : 1.f;
                ax = f1 * ax + f2 * vv.x;
                bx = f1 * bx + f2;
                px = ge ? pw : kk.x;
            }
            {   // state update y
                float pw = py + wy;
                float d  = pw - kk.y;
                bool  ge = (d >= 0.f);
                float e  = __expf(ge ? -d : d);
                float f1 = ge ? 1.f : e;
                float f2 = ge ? e   : 1.f;
                ay = f1 * ay + f2 * vv.y;
                by = f1 * by + f2;
                py = ge ? pw : kk.y;
            }
        }
    }
}

// mix: rh <- fp16(r * 0.5 * (wf + wb))
__global__ void mix_kernel(const __half* __restrict__ r,
                           const __half* __restrict__ wf,
                           const __half* __restrict__ wb,
                           __half* __restrict__ rh) {
    size_t i = ((size_t)blockIdx.x * blockDim.x + threadIdx.x) * 8;
    uint4 rv = *(const uint4*)(r + i);
    uint4 fv = *(const uint4*)(wf + i);
    uint4 bv = *(const uint4*)(wb + i);
    uint4 ov;
    const uint32_t* rp = &rv.x;
    const uint32_t* fp = &fv.x;
    const uint32_t* bp = &bv.x;
    uint32_t* op = &ov.x;
    #pragma unroll
    for (int j = 0; j < 4; j++) {
        float2 rr = __half22float2(*(const __half2*)&rp[j]);
        float2 ff = __half22float2(*(const __half2*)&fp[j]);
        float2 bbv = __half22float2(*(const __half2*)&bp[j]);
        __half2 h = __floats2half2_rn(rr.x * 0.5f * (ff.x + bbv.x),
                                      rr.y * 0.5f * (ff.y + bbv.y));
        op[j] = *(uint32_t*)&h;
    }
    *(uint4*)(rh + i) = ov;
}

// ---------------------------------------------------------------------------
// Launch
// ---------------------------------------------------------------------------
extern "C" void kernel_launch(void* const* d_in, const int* in_sizes, int n_in,
                              void* d_out, int out_size) {
    const float* x     = (const float*)d_in[0];
    const float* ln1w  = (const float*)d_in[1];
    const float* ln1b  = (const float*)d_in[2];
    const float* ln2w  = (const float*)d_in[3];
    const float* ln2b  = (const float*)d_in[4];
    const float* Wr    = (const float*)d_in[5];
    const float* Wk    = (const float*)d_in[6];
    const float* Wv    = (const float*)d_in[7];
    const float* Wo    = (const float*)d_in[8];
    const float* decay = (const float*)d_in[9];
    const float* u     = (const float*)d_in[10];
    const float* Wfk   = (const float*)d_in[11];
    const float* Wfv   = (const float*)d_in[12];
    const float* Wfr   = (const float*)d_in[13];
    float* out = (float*)d_out;

    __half *rs, *k, *v, *wf, *wb, *xnh, *rh, *kkh;
    __half *hWkv, *hWo, *hWffn, *hWfv;
    cudaGetSymbolAddress((void**)&rs,  g_rs);
    cudaGetSymbolAddress((void**)&k,   g_k);
    cudaGetSymbolAddress((void**)&v,   g_v);
    cudaGetSymbolAddress((void**)&wf,  g_wf);
    cudaGetSymbolAddress((void**)&wb,  g_wb);
    cudaGetSymbolAddress((void**)&xnh, g_xnh);
    cudaGetSymbolAddress((void**)&rh,  g_rh);
    cudaGetSymbolAddress((void**)&kkh, g_kkh);
    cudaGetSymbolAddress((void**)&hWkv,  g_wkv);
    cudaGetSymbolAddress((void**)&hWo,   g_wo);
    cudaGetSymbolAddress((void**)&hWffn, g_wffn);
    cudaGetSymbolAddress((void**)&hWfv,  g_wfv);

    const int smem = 2 * STG_BYTES + 256;  // 64KB + align pad
    cudaFuncSetAttribute(gemm_h<EPI_ADD>,  cudaFuncAttributeMaxDynamicSharedMemorySize, smem);
    cudaFuncSetAttribute(gemm_h<EPI_MADD>, cudaFuncAttributeMaxDynamicSharedMemorySize, smem);
    cudaFuncSetAttribute(gemm_h<EPI_RKV>,  cudaFuncAttributeMaxDynamicSharedMemorySize, smem);
    cudaFuncSetAttribute(gemm_h<EPI_FFN1>, cudaFuncAttributeMaxDynamicSharedMemorySize, smem);

    dim3 gRKV (3*CC / 128, MM / 128);   // (24, 64)
    dim3 gC   (CC / 128,   MM / 128);   // (8, 64)
    dim3 gFFN ((C4+CC)/128, MM / 128);  // (40, 64)

    // 0) convert + pack all weights to fp16 in ONE launch
    cvt_all_kernel<<<13 * 128, 512>>>(Wr, Wk, Wv, Wo, Wfk, Wfv, Wfr,
                                      hWkv, hWo, hWffn, hWfv);
    // 1) ln1 -> fp16
    ln_kernel<<<MM, 256>>>(x, ln1w, ln1b, xnh);
    // 2) fused r|k|v projection -> fp16 r (sigmoid), k, v
    gemm_h<EPI_RKV><<<gRKV, 256, smem>>>(xnh, hWkv, nullptr, rs, k, v,
                                         nullptr, nullptr, CC);
    // 3) bidirectional wkv scan (chunked two-pass, 2 channels/thread)
    scan2_kernel<<<dim3(CC / 64, BBATCH, 2), 512>>>(decay, u, k, v, wf, wb);
    // 4) rh = fp16(r * 0.5*(wf+wb))
    mix_kernel<<<(MM * CC) / 2048, 256>>>(rs, wf, wb, rh);
    // 5) out = x + (r*wkv) @ Wo^T
    gemm_h<EPI_ADD><<<gC, 256, smem>>>(rh, hWo, out, nullptr, nullptr, nullptr,
                                       x, nullptr, CC);
    // 6) ln2 -> fp16
    ln_kernel<<<MM, 256>>>(out, ln2w, ln2b, xnh);
    // 7) fused ffn1: kk = fp16(relu^2), gate = fp16 sigmoid (into rs)
    gemm_h<EPI_FFN1><<<gFFN, 256, smem>>>(xnh, hWffn, nullptr, kkh, rs, nullptr,
                                          nullptr, nullptr, CC);
    // 8) out += gate * (kk @ Wfv^T)
    gemm_h<EPI_MADD><<<gC, 256, smem>>>(kkh, hWfv, out, nullptr, nullptr, nullptr,
                                        out, rs, C4);
}